// round 10
// baseline (speedup 1.0000x reference)
#include <cuda_runtime.h>
#include <cuda_fp16.h>
#include <cuda_bf16.h>
#include <math.h>
#include <stdint.h>

#define EMBED_DIM 512
#define NUM_HEADS 8
#define HEAD_DIM 64
#define T_LEN 128
#define BATCH 8
#define BH 64
#define SCALING 0.125f
#define LAMBDA 1.0f

// Scratch (allocation-free rule: __device__ globals)
__device__ float g_q[BH * T_LEN * HEAD_DIM];     // [i][t][hd], scaled
__device__ float g_k[BH * T_LEN * HEAD_DIM];
__device__ float g_v[BH * T_LEN * HEAD_DIM];
__device__ float g_attn2[T_LEN * BATCH * EMBED_DIM];  // [t][b][h*64+d]

// ---------------------------------------------------------------------------
// helpers (base ISA only: ldmatrix + mma.sync)
// ---------------------------------------------------------------------------
__device__ __forceinline__ uint32_t smem_u32(const void* p) {
    uint32_t a;
    asm("{ .reg .u64 t; cvta.to.shared.u64 t, %1; cvt.u32.u64 %0, t; }"
        : "=r"(a) : "l"(p));
    return a;
}

__device__ __forceinline__ void ldmatrix_x4(uint32_t& r0, uint32_t& r1,
                                            uint32_t& r2, uint32_t& r3,
                                            uint32_t addr) {
    asm volatile("ldmatrix.sync.aligned.m8n8.x4.shared.b16 {%0,%1,%2,%3}, [%4];"
                 : "=r"(r0), "=r"(r1), "=r"(r2), "=r"(r3) : "r"(addr));
}

__device__ __forceinline__ void mma_f16(float* c, uint32_t a0, uint32_t a1,
                                        uint32_t a2, uint32_t a3,
                                        uint32_t b0, uint32_t b1) {
    asm volatile(
        "mma.sync.aligned.m16n8k16.row.col.f32.f16.f16.f32 "
        "{%0,%1,%2,%3}, {%4,%5,%6,%7}, {%8,%9}, {%0,%1,%2,%3};"
        : "+f"(c[0]), "+f"(c[1]), "+f"(c[2]), "+f"(c[3])
        : "r"(a0), "r"(a1), "r"(a2), "r"(a3), "r"(b0), "r"(b1));
}

// pack two fp32 into f16x2 word: low16 = x0, high16 = x1
__device__ __forceinline__ uint32_t cvt_f16x2(float x1, float x0) {
    uint32_t w;
    asm("cvt.rn.f16x2.f32 %0, %1, %2;" : "=r"(w) : "f"(x1), "f"(x0));
    return w;
}

// hi/lo split of 4 floats into packed f16 words (hi = rn(x), lo = rn(x - hi))
__device__ __forceinline__ void split4(float4 v, uint32_t& h0, uint32_t& h1,
                                       uint32_t& l0, uint32_t& l1) {
    h0 = cvt_f16x2(v.y, v.x);
    h1 = cvt_f16x2(v.w, v.z);
    float hx = __half2float(__ushort_as_half((unsigned short)(h0 & 0xFFFF)));
    float hy = __half2float(__ushort_as_half((unsigned short)(h0 >> 16)));
    float hz = __half2float(__ushort_as_half((unsigned short)(h1 & 0xFFFF)));
    float hw = __half2float(__ushort_as_half((unsigned short)(h1 >> 16)));
    l0 = cvt_f16x2(v.y - hy, v.x - hx);
    l1 = cvt_f16x2(v.w - hw, v.z - hz);
}

// SMEM layout (bytes). Rows padded to 144B (64 f16 + 8 pad) => conflict-free.
#define ROWB 144
#define SM_V     0                /* 128 * 144 = 18432 */
#define SM_QS    18432            /* [128][64] f32 = 32768 */
#define SM_FUSED 51200            /* [64][128] f32 = 32768 */
#define SM_TOTAL 83968

// ---------------------------------------------------------------------------
// Projection GEMM on tensor cores, 3-term fp16 hi/lo split, double-buffered.
// C[64rows x 64cols] tile per 128-thread block; K=512 in chunks of 64.
// One __syncthreads per chunk; chunk kc+1 load/split overlaps chunk kc mma.
// ---------------------------------------------------------------------------
#define PJ_XH 0
#define PJ_XL 9216
#define PJ_WH 18432
#define PJ_WL 27648
#define PJ_BUF 36864

__global__ __launch_bounds__(128) void gemm_proj_kernel(
    const float* __restrict__ xq, const float* __restrict__ xk,
    const float* __restrict__ xv, const float* __restrict__ W,
    const float* __restrict__ bias, float* __restrict__ outp, int mode)
{
    const int jbase = blockIdx.x * 64;
    const int rbase = blockIdx.y * 64;

    int section = 0;
    const float* __restrict__ X;
    if (mode == 0) {
        section = jbase >> 9;
        X = (section == 0) ? xq : (section == 1) ? xk : xv;
    } else {
        X = g_attn2;
    }

    extern __shared__ char psm[];
    const uint32_t sbase = smem_u32(psm);

    const int tid = threadIdx.x;
    const int wid = tid >> 5;
    const int lane = tid & 31;

    // load-phase: thread owns row=tid/2 (0..63), half th
    const int row = tid >> 1;
    const int th = (tid & 1) * 32;
    const float* __restrict__ xsrc = X + (size_t)(rbase + row) * 512 + th;
    const float* __restrict__ wsrc = W + (size_t)(jbase + row) * 512 + th;
    const int ld_off = row * ROWB + th * 2;

    // ldmatrix base addresses (buffer offset added per chunk)
    const uint32_t a_ldh0 = sbase + PJ_XH + (wid * 16 + (lane & 15)) * ROWB +
                            ((lane >= 16) ? 16 : 0);
    const uint32_t b_ldh0 = sbase + PJ_WH + (lane & 7) * ROWB + ((lane >> 3) * 16);

    float acc[8][4];
#pragma unroll
    for (int n = 0; n < 8; n++)
#pragma unroll
        for (int j = 0; j < 4; j++) acc[n][j] = 0.f;

    // chunk loader: load 64-wide k-chunk kc into buffer (kc&1)
    auto loadchunk = [&](int kc) {
        char* base = psm + (kc & 1) * PJ_BUF;
        const int k0 = kc * 64;
        char* xh = base + PJ_XH + ld_off;
        char* xl = base + PJ_XL + ld_off;
        char* wh = base + PJ_WH + ld_off;
        char* wl = base + PJ_WL + ld_off;
#pragma unroll
        for (int j = 0; j < 32; j += 4) {
            float4 v4 = *(const float4*)&xsrc[k0 + j];
            uint32_t h0, h1, l0, l1;
            split4(v4, h0, h1, l0, l1);
            *(uint2*)(xh + j * 2) = make_uint2(h0, h1);
            *(uint2*)(xl + j * 2) = make_uint2(l0, l1);
            float4 w4 = *(const float4*)&wsrc[k0 + j];
            split4(w4, h0, h1, l0, l1);
            *(uint2*)(wh + j * 2) = make_uint2(h0, h1);
            *(uint2*)(wl + j * 2) = make_uint2(l0, l1);
        }
    };

    loadchunk(0);
    __syncthreads();

#pragma unroll 1
    for (int kc = 0; kc < 8; kc++) {
        const uint32_t boff = (kc & 1) * PJ_BUF;
        // start next chunk's loads (writes the OTHER buffer) before mma
        if (kc < 7) loadchunk(kc + 1);

        const uint32_t a_ldh = a_ldh0 + boff;
        const uint32_t a_ldl = a_ldh + (PJ_XL - PJ_XH);
        const uint32_t b_ldh = b_ldh0 + boff;
        const uint32_t b_ldl = b_ldh + (PJ_WL - PJ_WH);

        uint32_t ah[16], al[16];
#pragma unroll
        for (int ks = 0; ks < 4; ks++) {
            ldmatrix_x4(ah[ks * 4 + 0], ah[ks * 4 + 1], ah[ks * 4 + 2],
                        ah[ks * 4 + 3], a_ldh + ks * 32);
            ldmatrix_x4(al[ks * 4 + 0], al[ks * 4 + 1], al[ks * 4 + 2],
                        al[ks * 4 + 3], a_ldl + ks * 32);
        }

#pragma unroll
        for (int nc = 0; nc < 8; nc++) {
            uint32_t bh[8], bl[8];
            ldmatrix_x4(bh[0], bh[1], bh[2], bh[3], b_ldh + nc * (8 * ROWB));
            ldmatrix_x4(bh[4], bh[5], bh[6], bh[7], b_ldh + nc * (8 * ROWB) + 64);
            ldmatrix_x4(bl[0], bl[1], bl[2], bl[3], b_ldl + nc * (8 * ROWB));
            ldmatrix_x4(bl[4], bl[5], bl[6], bl[7], b_ldl + nc * (8 * ROWB) + 64);
#pragma unroll
            for (int ks = 0; ks < 4; ks++) {
                mma_f16(acc[nc], ah[ks * 4 + 0], ah[ks * 4 + 1], ah[ks * 4 + 2],
                        ah[ks * 4 + 3], bh[ks * 2], bh[ks * 2 + 1]);
                mma_f16(acc[nc], ah[ks * 4 + 0], ah[ks * 4 + 1], ah[ks * 4 + 2],
                        ah[ks * 4 + 3], bl[ks * 2], bl[ks * 2 + 1]);
                mma_f16(acc[nc], al[ks * 4 + 0], al[ks * 4 + 1], al[ks * 4 + 2],
                        al[ks * 4 + 3], bh[ks * 2], bh[ks * 2 + 1]);
            }
        }
        __syncthreads();
    }

    // epilogue: fragment (row r0/r0+8, col jg/jg+1) per acc[nc]
    const int g = lane >> 2;
    const int tig = lane & 3;
    const int r0 = rbase + wid * 16 + g;

#pragma unroll
    for (int nc = 0; nc < 8; nc++) {
        const int jg = jbase + nc * 8 + 2 * tig;
        const float b0 = bias[jg], b1 = bias[jg + 1];
        float v00 = acc[nc][0] + b0, v01 = acc[nc][1] + b1;
        float v10 = acc[nc][2] + b0, v11 = acc[nc][3] + b1;
        if (mode == 0) {
            if (section == 0) { v00 *= SCALING; v01 *= SCALING;
                                v10 *= SCALING; v11 *= SCALING; }
            float* dst = (section == 0) ? g_q : (section == 1) ? g_k : g_v;
            const int jj = jg & 511;
            const int h = jj >> 6;
            const int dp = jj & 63;
#pragma unroll
            for (int rr = 0; rr < 2; rr++) {
                const int r = r0 + rr * 8;
                const int t = r >> 3;
                const int bb = r & 7;
                float2 val = rr ? make_float2(v10, v11) : make_float2(v00, v01);
                *(float2*)&dst[(((size_t)(bb * 8 + h)) * 128 + t) * 64 + dp] = val;
            }
        } else {
            *(float2*)&outp[(size_t)r0 * 512 + jg] = make_float2(v00, v01);
            *(float2*)&outp[(size_t)(r0 + 8) * 512 + jg] = make_float2(v10, v11);
        }
    }
}

// ---------------------------------------------------------------------------
// Kernel B v8: v7 + software-pipelined bias loads (prefetch nc+1).
// ---------------------------------------------------------------------------
__global__ __launch_bounds__(512, 1) void tri_main_v8(const float* __restrict__ cbias)
{
    const int head  = blockIdx.x;   // 0..7
    const int ahalf = blockIdx.y;   // 0..1
    const int batch = blockIdx.z;   // 0..7
    const int i = batch * 8 + head;
    const int a0 = ahalf * 64;

    extern __shared__ char smem[];
    const uint32_t sbase = smem_u32(smem);
    float* qs    = (float*)(smem + SM_QS);
    float* fused = (float*)(smem + SM_FUSED);

    const int tid  = threadIdx.x;
    const int wid  = tid >> 5;       // 0..15
    const int lane = tid & 31;
    const int bwin = (wid & 7) * 16; // b-row window
    const int asub = (wid >> 3) * 32;

    const float* __restrict__ qi = g_q + (size_t)i * 8192;
    const float* __restrict__ ki = g_k + (size_t)i * 8192;
    const float* __restrict__ vi = g_v + (size_t)i * 8192;

    // qs <- full q (scaled), needed by prep and final bmm
    for (int idx = tid; idx < 8192; idx += 512) qs[idx] = qi[idx];

    // V -> fp16 padded rows. thread: row=tid/4, 16-elem quarter
    {
        const int row = tid >> 2;
        const int tq = (tid & 3) * 16;
        char* vd = smem + SM_V + row * ROWB;
        const float* src = vi + row * 64 + tq;
#pragma unroll
        for (int j = 0; j < 16; j += 4) {
            uint32_t w0 = cvt_f16x2(src[j + 1], src[j]);
            uint32_t w1 = cvt_f16x2(src[j + 3], src[j + 2]);
            *(uint2*)(vd + (tq + j) * 2) = make_uint2(w0, w1);
        }
    }

    const int g = lane >> 2;       // fragment row group
    const int tig = lane & 3;      // fragment col pair

    // K values this lane needs for A fragments: rows bwin+g, bwin+g+8;
    // cols 16*ks + 2*tig + {0,1,8,9}
    float kr0[16], kr1[16];
    {
        const float* krow0 = ki + (size_t)(bwin + g) * 64;
        const float* krow1 = krow0 + 8 * 64;
#pragma unroll
        for (int ks = 0; ks < 4; ks++) {
            int c = ks * 16 + 2 * tig;
            kr0[ks * 4 + 0] = krow0[c];     kr0[ks * 4 + 1] = krow0[c + 1];
            kr0[ks * 4 + 2] = krow0[c + 8]; kr0[ks * 4 + 3] = krow0[c + 9];
            kr1[ks * 4 + 0] = krow1[c];     kr1[ks * 4 + 1] = krow1[c + 1];
            kr1[ks * 4 + 2] = krow1[c + 8]; kr1[ks * 4 + 3] = krow1[c + 9];
        }
    }
    __syncthreads();

    // V ldmatrix base: x4 tiles = 4 consecutive k-octets of 8 n-rows
    const uint32_t v_ld = sbase + SM_V + (lane & 7) * ROWB + ((lane >> 3) * 16);

    const int browA = bwin + g;
    const int colbase = 2 * tig;
    const float* __restrict__ bias_b = cbias + ((size_t)batch << 21);

#pragma unroll 1
    for (int ap = 0; ap < 16; ap++) {
        const int aA = asub + 2 * ap, aB = aA + 1;

        // ---- build A fragments for both a's directly in registers ----
        uint32_t fa0[16], fa1[16];   // [ks*4 + r]
        {
            const float* qA = qs + (a0 + aA) * 64;
            const float* qB = qA + 64;
#pragma unroll
            for (int ks = 0; ks < 4; ks++) {
                int c = ks * 16 + 2 * tig;
                float2 qa01 = *(const float2*)&qA[c];
                float2 qa89 = *(const float2*)&qA[c + 8];
                float2 qb01 = *(const float2*)&qB[c];
                float2 qb89 = *(const float2*)&qB[c + 8];
                fa0[ks * 4 + 0] = cvt_f16x2(kr0[ks * 4 + 1] * qa01.y, kr0[ks * 4 + 0] * qa01.x);
                fa0[ks * 4 + 1] = cvt_f16x2(kr1[ks * 4 + 1] * qa01.y, kr1[ks * 4 + 0] * qa01.x);
                fa0[ks * 4 + 2] = cvt_f16x2(kr0[ks * 4 + 3] * qa89.y, kr0[ks * 4 + 2] * qa89.x);
                fa0[ks * 4 + 3] = cvt_f16x2(kr1[ks * 4 + 3] * qa89.y, kr1[ks * 4 + 2] * qa89.x);
                fa1[ks * 4 + 0] = cvt_f16x2(kr0[ks * 4 + 1] * qb01.y, kr0[ks * 4 + 0] * qb01.x);
                fa1[ks * 4 + 1] = cvt_f16x2(kr1[ks * 4 + 1] * qb01.y, kr1[ks * 4 + 0] * qb01.x);
                fa1[ks * 4 + 2] = cvt_f16x2(kr0[ks * 4 + 3] * qb89.y, kr0[ks * 4 + 2] * qb89.x);
                fa1[ks * 4 + 3] = cvt_f16x2(kr1[ks * 4 + 3] * qb89.y, kr1[ks * 4 + 2] * qb89.x);
            }
        }

        const float* __restrict__ bpA =
            bias_b + ((size_t)(a0 + aA) << 14) + (size_t)browA * 128;
        const float* __restrict__ bpB = bpA + (1 << 14);
        float psA0 = 0.f, psA1 = 0.f, pmA0 = -1e30f, pmA1 = -1e30f;
        float psB0 = 0.f, psB1 = 0.f, pmB0 = -1e30f, pmB1 = -1e30f;

        // prefetch bias for nc=0
        float2 nA0 = *(const float2*)&bpA[colbase];
        float2 nA1 = *(const float2*)&bpA[8 * 128 + colbase];
        float2 nB0 = *(const float2*)&bpB[colbase];
        float2 nB1 = *(const float2*)&bpB[8 * 128 + colbase];

#pragma unroll 2
        for (int nc = 0; nc < 16; nc++) {
            float2 bA0 = nA0, bA1 = nA1, bB0 = nB0, bB1 = nB1;
            if (nc < 15) {
                const int col = (nc + 1) * 8 + colbase;
                nA0 = *(const float2*)&bpA[col];
                nA1 = *(const float2*)&bpA[8 * 128 + col];
                nB0 = *(const float2*)&bpB[col];
                nB1 = *(const float2*)&bpB[8 * 128 + col];
            }
            uint32_t b[8];
            ldmatrix_x4(b[0], b[1], b[2], b[3], v_ld + nc * (8 * ROWB));
            ldmatrix_x4(b[4], b[5], b[6], b[7], v_ld + nc * (8 * ROWB) + 64);
            float c0[4] = {0.f, 0.f, 0.f, 0.f};
            float c1[4] = {0.f, 0.f, 0.f, 0.f};
#pragma unroll
            for (int ks = 0; ks < 4; ks++) {
                mma_f16(c0, fa0[ks * 4 + 0], fa0[ks * 4 + 1], fa0[ks * 4 + 2],
                        fa0[ks * 4 + 3], b[ks * 2], b[ks * 2 + 1]);
                mma_f16(c1, fa1[ks * 4 + 0], fa1[ks * 4 + 1], fa1[ks * 4 + 2],
                        fa1[ks * 4 + 3], b[ks * 2], b[ks * 2 + 1]);
            }
            {
                float s0 = c0[0] + bA0.x, s1 = c0[1] + bA0.y;
                float s2 = c0[2] + bA1.x, s3 = c0[3] + bA1.y;
                psA0 += s0 + s1; psA1 += s2 + s3;
                pmA0 = fmaxf(pmA0, fmaxf(s0, s1));
                pmA1 = fmaxf(pmA1, fmaxf(s2, s3));
            }
            {
                float s0 = c1[0] + bB0.x, s1 = c1[1] + bB0.y;
                float s2 = c1[2] + bB1.x, s3 = c1[3] + bB1.y;
                psB0 += s0 + s1; psB1 += s2 + s3;
                pmB0 = fmaxf(pmB0, fmaxf(s0, s1));
                pmB1 = fmaxf(pmB1, fmaxf(s2, s3));
            }
        }
        // quad reduce (cols spread over 4 tig lanes)
#pragma unroll
        for (int off = 1; off <= 2; off <<= 1) {
            psA0 += __shfl_xor_sync(0xffffffffu, psA0, off);
            psA1 += __shfl_xor_sync(0xffffffffu, psA1, off);
            psB0 += __shfl_xor_sync(0xffffffffu, psB0, off);
            psB1 += __shfl_xor_sync(0xffffffffu, psB1, off);
            pmA0 = fmaxf(pmA0, __shfl_xor_sync(0xffffffffu, pmA0, off));
            pmA1 = fmaxf(pmA1, __shfl_xor_sync(0xffffffffu, pmA1, off));
            pmB0 = fmaxf(pmB0, __shfl_xor_sync(0xffffffffu, pmB0, off));
            pmB1 = fmaxf(pmB1, __shfl_xor_sync(0xffffffffu, pmB1, off));
        }
        if (tig == 0) {
            fused[aA * 128 + browA]     = psA0 * (1.0f / 128.0f) + pmA0;
            fused[aA * 128 + browA + 8] = psA1 * (1.0f / 128.0f) + pmA1;
            fused[aB * 128 + browA]     = psB0 * (1.0f / 128.0f) + pmB0;
            fused[aB * 128 + browA + 8] = psB1 * (1.0f / 128.0f) + pmB1;
        }
    }
    __syncthreads();

    // Softmax over b for each of the 64 rows (one warp per row, round-robin)
    for (int a = wid; a < 64; a += 16) {
        float4 fv = *(float4*)&fused[a * 128 + lane * 4];
        float m = fmaxf(fmaxf(fv.x, fv.y), fmaxf(fv.z, fv.w));
#pragma unroll
        for (int off = 16; off >= 1; off >>= 1)
            m = fmaxf(m, __shfl_xor_sync(0xffffffffu, m, off));
        float e0 = __expf(fv.x - m), e1 = __expf(fv.y - m);
        float e2 = __expf(fv.z - m), e3 = __expf(fv.w - m);
        float s = (e0 + e1) + (e2 + e3);
#pragma unroll
        for (int off = 16; off >= 1; off >>= 1)
            s += __shfl_xor_sync(0xffffffffu, s, off);
        float inv = 1.0f / s;
        *(float4*)&fused[a * 128 + lane * 4] =
            make_float4(e0 * inv, e1 * inv, e2 * inv, e3 * inv);
    }
    __syncthreads();

    // attn[a, :] = sum_b w[a,b] q[b,:]; thread: a=tid/8 (64 rows), 8 cols
    {
        int a = tid >> 3;
        int dg = (tid & 7) * 8;
        float o[8];
#pragma unroll
        for (int j = 0; j < 8; j++) o[j] = 0.f;
        const float* wrow = fused + a * 128;
#pragma unroll 4
        for (int b = 0; b < 128; b++) {
            float wb = wrow[b];
            const float* qr = qs + b * 64 + dg;
            float4 q0 = *(const float4*)&qr[0];
            float4 q1 = *(const float4*)&qr[4];
            o[0] += wb * q0.x; o[1] += wb * q0.y;
            o[2] += wb * q0.z; o[3] += wb * q0.w;
            o[4] += wb * q1.x; o[5] += wb * q1.y;
            o[6] += wb * q1.z; o[7] += wb * q1.w;
        }
        int t = a0 + a;
        float* dst = g_attn2 + ((size_t)t * 8 + batch) * 512 + head * 64 + dg;
        *(float4*)&dst[0] = make_float4(o[0], o[1], o[2], o[3]);
        *(float4*)&dst[4] = make_float4(o[4], o[5], o[6], o[7]);
    }
}

// ---------------------------------------------------------------------------
extern "C" void kernel_launch(void* const* d_in, const int* in_sizes, int n_in,
                              void* d_out, int out_size)
{
    const float* query = (const float*)d_in[0];
    const float* key   = (const float*)d_in[1];
    const float* value = (const float*)d_in[2];
    const float* cbias = (const float*)d_in[3];
    const float* ipw   = (const float*)d_in[4];
    const float* ipb   = (const float*)d_in[5];
    const float* outw  = (const float*)d_in[6];
    const float* outb  = (const float*)d_in[7];
    float* out = (float*)d_out;

    cudaFuncSetAttribute(gemm_proj_kernel,
                         cudaFuncAttributeMaxDynamicSharedMemorySize,
                         2 * PJ_BUF);
    // in-projection on tensor cores (3-term fp16 split, fp32-accurate)
    gemm_proj_kernel<<<dim3(24, 16), 128, 2 * PJ_BUF>>>(query, key, value, ipw,
                                                        ipb, nullptr, 0);

    cudaFuncSetAttribute(tri_main_v8,
                         cudaFuncAttributeMaxDynamicSharedMemorySize, SM_TOTAL);
    tri_main_v8<<<dim3(8, 2, 8), 512, SM_TOTAL>>>(cbias);

    // out-projection (X = g_attn2 selected inside kernel via mode=1)
    gemm_proj_kernel<<<dim3(8, 16), 128, 2 * PJ_BUF>>>(nullptr, nullptr,
                                                       nullptr, outw, outb,
                                                       out, 1);
}

// round 11
// speedup vs baseline: 1.0520x; 1.0520x over previous
#include <cuda_runtime.h>
#include <cuda_fp16.h>
#include <cuda_bf16.h>
#include <math.h>
#include <stdint.h>

#define EMBED_DIM 512
#define NUM_HEADS 8
#define HEAD_DIM 64
#define T_LEN 128
#define BATCH 8
#define BH 64
#define SCALING 0.125f
#define LAMBDA 1.0f

// Scratch (allocation-free rule: __device__ globals)
__device__ float g_q[BH * T_LEN * HEAD_DIM];     // [i][t][hd], scaled
__device__ float g_k[BH * T_LEN * HEAD_DIM];
__device__ float g_v[BH * T_LEN * HEAD_DIM];
__device__ float g_attn2[T_LEN * BATCH * EMBED_DIM];  // [t][b][h*64+d]

// ---------------------------------------------------------------------------
// helpers (base ISA only: ldmatrix + mma.sync)
// ---------------------------------------------------------------------------
__device__ __forceinline__ uint32_t smem_u32(const void* p) {
    uint32_t a;
    asm("{ .reg .u64 t; cvta.to.shared.u64 t, %1; cvt.u32.u64 %0, t; }"
        : "=r"(a) : "l"(p));
    return a;
}

__device__ __forceinline__ void ldmatrix_x4(uint32_t& r0, uint32_t& r1,
                                            uint32_t& r2, uint32_t& r3,
                                            uint32_t addr) {
    asm volatile("ldmatrix.sync.aligned.m8n8.x4.shared.b16 {%0,%1,%2,%3}, [%4];"
                 : "=r"(r0), "=r"(r1), "=r"(r2), "=r"(r3) : "r"(addr));
}

__device__ __forceinline__ void mma_f16(float* c, uint32_t a0, uint32_t a1,
                                        uint32_t a2, uint32_t a3,
                                        uint32_t b0, uint32_t b1) {
    asm volatile(
        "mma.sync.aligned.m16n8k16.row.col.f32.f16.f16.f32 "
        "{%0,%1,%2,%3}, {%4,%5,%6,%7}, {%8,%9}, {%0,%1,%2,%3};"
        : "+f"(c[0]), "+f"(c[1]), "+f"(c[2]), "+f"(c[3])
        : "r"(a0), "r"(a1), "r"(a2), "r"(a3), "r"(b0), "r"(b1));
}

// pack two fp32 into f16x2 word: low16 = x0, high16 = x1
__device__ __forceinline__ uint32_t cvt_f16x2(float x1, float x0) {
    uint32_t w;
    asm("cvt.rn.f16x2.f32 %0, %1, %2;" : "=r"(w) : "f"(x1), "f"(x0));
    return w;
}

// hi/lo split of 4 floats into packed f16 words (hi = rn(x), lo = rn(x - hi))
__device__ __forceinline__ void split4(float4 v, uint32_t& h0, uint32_t& h1,
                                       uint32_t& l0, uint32_t& l1) {
    h0 = cvt_f16x2(v.y, v.x);
    h1 = cvt_f16x2(v.w, v.z);
    float hx = __half2float(__ushort_as_half((unsigned short)(h0 & 0xFFFF)));
    float hy = __half2float(__ushort_as_half((unsigned short)(h0 >> 16)));
    float hz = __half2float(__ushort_as_half((unsigned short)(h1 & 0xFFFF)));
    float hw = __half2float(__ushort_as_half((unsigned short)(h1 >> 16)));
    l0 = cvt_f16x2(v.y - hy, v.x - hx);
    l1 = cvt_f16x2(v.w - hw, v.z - hz);
}

// SMEM layout (bytes). Rows padded to 144B (64 f16 + 8 pad) => conflict-free.
#define ROWB 144
#define SM_V     0                /* 128 * 144 = 18432 */
#define SM_QS    18432            /* [128][64] f32 = 32768 */
#define SM_FUSED 51200            /* [64][128] f32 = 32768 */
#define SM_TOTAL 83968

// ---------------------------------------------------------------------------
// Projection GEMM v3: tensor cores, 3-term fp16 hi/lo split (fp32-accurate),
// 256 threads, K-SPLIT across two 4-warp groups (chunks 0-3 / 4-7), each
// group in its own 36KB buffer. Partial C's summed through smem at the end.
// ---------------------------------------------------------------------------
#define PJ_XH 0
#define PJ_XL 9216
#define PJ_WH 18432
#define PJ_WL 27648
#define PJ_BUF 36864
#define PJ_TOTAL 73728

__global__ __launch_bounds__(256) void gemm_proj_kernel(
    const float* __restrict__ xq, const float* __restrict__ xk,
    const float* __restrict__ xv, const float* __restrict__ W,
    const float* __restrict__ bias, float* __restrict__ outp, int mode)
{
    const int jbase = blockIdx.x * 64;
    const int rbase = blockIdx.y * 64;

    int section = 0;
    const float* __restrict__ X;
    if (mode == 0) {
        section = jbase >> 9;
        X = (section == 0) ? xq : (section == 1) ? xk : xv;
    } else {
        X = g_attn2;
    }

    extern __shared__ char psm[];
    const uint32_t sbase = smem_u32(psm);

    const int tid = threadIdx.x;
    const int wid = tid >> 5;
    const int lane = tid & 31;
    const int kgrp = wid >> 2;       // 0: chunks 0-3, 1: chunks 4-7
    const int wg = wid & 3;          // warp within group -> 16-row band

    // load-phase (per group): ltid 0..127, row = ltid/2, half th
    const int ltid = tid & 127;
    const int row = ltid >> 1;
    const int th = (ltid & 1) * 32;
    const float* __restrict__ xsrc = X + (size_t)(rbase + row) * 512 + th;
    const float* __restrict__ wsrc = W + (size_t)(jbase + row) * 512 + th;
    char* mybuf = psm + kgrp * PJ_BUF;
    char* xh = mybuf + PJ_XH + row * ROWB + th * 2;
    char* xl = mybuf + PJ_XL + row * ROWB + th * 2;
    char* wh = mybuf + PJ_WH + row * ROWB + th * 2;
    char* wl = mybuf + PJ_WL + row * ROWB + th * 2;

    // ldmatrix addresses within this group's buffer
    const uint32_t gb = sbase + kgrp * PJ_BUF;
    const uint32_t a_ldh = gb + PJ_XH + (wg * 16 + (lane & 15)) * ROWB +
                           ((lane >= 16) ? 16 : 0);
    const uint32_t a_ldl = a_ldh + (PJ_XL - PJ_XH);
    const uint32_t b_ldh = gb + PJ_WH + (lane & 7) * ROWB + ((lane >> 3) * 16);
    const uint32_t b_ldl = b_ldh + (PJ_WL - PJ_WH);

    float acc[8][4];
#pragma unroll
    for (int n = 0; n < 8; n++)
#pragma unroll
        for (int j = 0; j < 4; j++) acc[n][j] = 0.f;

#pragma unroll 1
    for (int j = 0; j < 4; j++) {
        const int k0 = (kgrp * 4 + j) * 64;
        // load & hi/lo split this group's chunk into its buffer
#pragma unroll
        for (int jj = 0; jj < 32; jj += 4) {
            float4 v4 = *(const float4*)&xsrc[k0 + jj];
            uint32_t h0, h1, l0, l1;
            split4(v4, h0, h1, l0, l1);
            *(uint2*)(xh + jj * 2) = make_uint2(h0, h1);
            *(uint2*)(xl + jj * 2) = make_uint2(l0, l1);
            float4 w4 = *(const float4*)&wsrc[k0 + jj];
            split4(w4, h0, h1, l0, l1);
            *(uint2*)(wh + jj * 2) = make_uint2(h0, h1);
            *(uint2*)(wl + jj * 2) = make_uint2(l0, l1);
        }
        __syncthreads();

        uint32_t ah[16], al[16];
#pragma unroll
        for (int ks = 0; ks < 4; ks++) {
            ldmatrix_x4(ah[ks * 4 + 0], ah[ks * 4 + 1], ah[ks * 4 + 2],
                        ah[ks * 4 + 3], a_ldh + ks * 32);
            ldmatrix_x4(al[ks * 4 + 0], al[ks * 4 + 1], al[ks * 4 + 2],
                        al[ks * 4 + 3], a_ldl + ks * 32);
        }

#pragma unroll
        for (int nc = 0; nc < 8; nc++) {
            uint32_t bh[8], bl[8];
            ldmatrix_x4(bh[0], bh[1], bh[2], bh[3], b_ldh + nc * (8 * ROWB));
            ldmatrix_x4(bh[4], bh[5], bh[6], bh[7], b_ldh + nc * (8 * ROWB) + 64);
            ldmatrix_x4(bl[0], bl[1], bl[2], bl[3], b_ldl + nc * (8 * ROWB));
            ldmatrix_x4(bl[4], bl[5], bl[6], bl[7], b_ldl + nc * (8 * ROWB) + 64);
#pragma unroll
            for (int ks = 0; ks < 4; ks++) {
                mma_f16(acc[nc], ah[ks * 4 + 0], ah[ks * 4 + 1], ah[ks * 4 + 2],
                        ah[ks * 4 + 3], bh[ks * 2], bh[ks * 2 + 1]);
                mma_f16(acc[nc], ah[ks * 4 + 0], ah[ks * 4 + 1], ah[ks * 4 + 2],
                        ah[ks * 4 + 3], bl[ks * 2], bl[ks * 2 + 1]);
                mma_f16(acc[nc], al[ks * 4 + 0], al[ks * 4 + 1], al[ks * 4 + 2],
                        al[ks * 4 + 3], bh[ks * 2], bh[ks * 2 + 1]);
            }
        }
        __syncthreads();
    }

    // cross-group reduction: group 1 spills partial C into group 0's dead
    // buffer region (16KB), group 0 adds and does the epilogue.
    float* red = (float*)psm;
    const int rbidx = ((wg * 32 + lane) * 8) * 4;
    if (kgrp == 1) {
#pragma unroll
        for (int nc = 0; nc < 8; nc++)
            *(float4*)&red[rbidx + nc * 4] =
                make_float4(acc[nc][0], acc[nc][1], acc[nc][2], acc[nc][3]);
    }
    __syncthreads();
    if (kgrp == 0) {
        const int g = lane >> 2;
        const int tig = lane & 3;
        const int r0 = rbase + wg * 16 + g;
#pragma unroll
        for (int nc = 0; nc < 8; nc++) {
            float4 r = *(const float4*)&red[rbidx + nc * 4];
            const int jg = jbase + nc * 8 + 2 * tig;
            const float b0 = bias[jg], b1 = bias[jg + 1];
            float v00 = acc[nc][0] + r.x + b0, v01 = acc[nc][1] + r.y + b1;
            float v10 = acc[nc][2] + r.z + b0, v11 = acc[nc][3] + r.w + b1;
            if (mode == 0) {
                if (section == 0) { v00 *= SCALING; v01 *= SCALING;
                                    v10 *= SCALING; v11 *= SCALING; }
                float* dst = (section == 0) ? g_q : (section == 1) ? g_k : g_v;
                const int jj = jg & 511;
                const int h = jj >> 6;
                const int dp = jj & 63;
#pragma unroll
                for (int rr = 0; rr < 2; rr++) {
                    const int r2 = r0 + rr * 8;
                    const int t = r2 >> 3;
                    const int bb = r2 & 7;
                    float2 val = rr ? make_float2(v10, v11) : make_float2(v00, v01);
                    *(float2*)&dst[(((size_t)(bb * 8 + h)) * 128 + t) * 64 + dp] = val;
                }
            } else {
                *(float2*)&outp[(size_t)r0 * 512 + jg] = make_float2(v00, v01);
                *(float2*)&outp[(size_t)(r0 + 8) * 512 + jg] = make_float2(v10, v11);
            }
        }
    }
}

// ---------------------------------------------------------------------------
// Kernel B v8: fp16 mma.sync trilinear, register-built A fragments, 16 warps,
// software-pipelined bias loads. (frozen from R10 — tri_main portion ~128us)
// ---------------------------------------------------------------------------
__global__ __launch_bounds__(512, 1) void tri_main_v8(const float* __restrict__ cbias)
{
    const int head  = blockIdx.x;   // 0..7
    const int ahalf = blockIdx.y;   // 0..1
    const int batch = blockIdx.z;   // 0..7
    const int i = batch * 8 + head;
    const int a0 = ahalf * 64;

    extern __shared__ char smem[];
    const uint32_t sbase = smem_u32(smem);
    float* qs    = (float*)(smem + SM_QS);
    float* fused = (float*)(smem + SM_FUSED);

    const int tid  = threadIdx.x;
    const int wid  = tid >> 5;       // 0..15
    const int lane = tid & 31;
    const int bwin = (wid & 7) * 16; // b-row window
    const int asub = (wid >> 3) * 32;

    const float* __restrict__ qi = g_q + (size_t)i * 8192;
    const float* __restrict__ ki = g_k + (size_t)i * 8192;
    const float* __restrict__ vi = g_v + (size_t)i * 8192;

    // qs <- full q (scaled), needed by prep and final bmm
    for (int idx = tid; idx < 8192; idx += 512) qs[idx] = qi[idx];

    // V -> fp16 padded rows. thread: row=tid/4, 16-elem quarter
    {
        const int row = tid >> 2;
        const int tq = (tid & 3) * 16;
        char* vd = smem + SM_V + row * ROWB;
        const float* src = vi + row * 64 + tq;
#pragma unroll
        for (int j = 0; j < 16; j += 4) {
            uint32_t w0 = cvt_f16x2(src[j + 1], src[j]);
            uint32_t w1 = cvt_f16x2(src[j + 3], src[j + 2]);
            *(uint2*)(vd + (tq + j) * 2) = make_uint2(w0, w1);
        }
    }

    const int g = lane >> 2;       // fragment row group
    const int tig = lane & 3;      // fragment col pair

    // K values this lane needs for A fragments: rows bwin+g, bwin+g+8;
    // cols 16*ks + 2*tig + {0,1,8,9}
    float kr0[16], kr1[16];
    {
        const float* krow0 = ki + (size_t)(bwin + g) * 64;
        const float* krow1 = krow0 + 8 * 64;
#pragma unroll
        for (int ks = 0; ks < 4; ks++) {
            int c = ks * 16 + 2 * tig;
            kr0[ks * 4 + 0] = krow0[c];     kr0[ks * 4 + 1] = krow0[c + 1];
            kr0[ks * 4 + 2] = krow0[c + 8]; kr0[ks * 4 + 3] = krow0[c + 9];
            kr1[ks * 4 + 0] = krow1[c];     kr1[ks * 4 + 1] = krow1[c + 1];
            kr1[ks * 4 + 2] = krow1[c + 8]; kr1[ks * 4 + 3] = krow1[c + 9];
        }
    }
    __syncthreads();

    // V ldmatrix base: x4 tiles = 4 consecutive k-octets of 8 n-rows
    const uint32_t v_ld = sbase + SM_V + (lane & 7) * ROWB + ((lane >> 3) * 16);

    const int browA = bwin + g;
    const int colbase = 2 * tig;
    const float* __restrict__ bias_b = cbias + ((size_t)batch << 21);

#pragma unroll 1
    for (int ap = 0; ap < 16; ap++) {
        const int aA = asub + 2 * ap, aB = aA + 1;

        // ---- build A fragments for both a's directly in registers ----
        uint32_t fa0[16], fa1[16];   // [ks*4 + r]
        {
            const float* qA = qs + (a0 + aA) * 64;
            const float* qB = qA + 64;
#pragma unroll
            for (int ks = 0; ks < 4; ks++) {
                int c = ks * 16 + 2 * tig;
                float2 qa01 = *(const float2*)&qA[c];
                float2 qa89 = *(const float2*)&qA[c + 8];
                float2 qb01 = *(const float2*)&qB[c];
                float2 qb89 = *(const float2*)&qB[c + 8];
                fa0[ks * 4 + 0] = cvt_f16x2(kr0[ks * 4 + 1] * qa01.y, kr0[ks * 4 + 0] * qa01.x);
                fa0[ks * 4 + 1] = cvt_f16x2(kr1[ks * 4 + 1] * qa01.y, kr1[ks * 4 + 0] * qa01.x);
                fa0[ks * 4 + 2] = cvt_f16x2(kr0[ks * 4 + 3] * qa89.y, kr0[ks * 4 + 2] * qa89.x);
                fa0[ks * 4 + 3] = cvt_f16x2(kr1[ks * 4 + 3] * qa89.y, kr1[ks * 4 + 2] * qa89.x);
                fa1[ks * 4 + 0] = cvt_f16x2(kr0[ks * 4 + 1] * qb01.y, kr0[ks * 4 + 0] * qb01.x);
                fa1[ks * 4 + 1] = cvt_f16x2(kr1[ks * 4 + 1] * qb01.y, kr1[ks * 4 + 0] * qb01.x);
                fa1[ks * 4 + 2] = cvt_f16x2(kr0[ks * 4 + 3] * qb89.y, kr0[ks * 4 + 2] * qb89.x);
                fa1[ks * 4 + 3] = cvt_f16x2(kr1[ks * 4 + 3] * qb89.y, kr1[ks * 4 + 2] * qb89.x);
            }
        }

        const float* __restrict__ bpA =
            bias_b + ((size_t)(a0 + aA) << 14) + (size_t)browA * 128;
        const float* __restrict__ bpB = bpA + (1 << 14);
        float psA0 = 0.f, psA1 = 0.f, pmA0 = -1e30f, pmA1 = -1e30f;
        float psB0 = 0.f, psB1 = 0.f, pmB0 = -1e30f, pmB1 = -1e30f;

        // prefetch bias for nc=0
        float2 nA0 = *(const float2*)&bpA[colbase];
        float2 nA1 = *(const float2*)&bpA[8 * 128 + colbase];
        float2 nB0 = *(const float2*)&bpB[colbase];
        float2 nB1 = *(const float2*)&bpB[8 * 128 + colbase];

#pragma unroll 2
        for (int nc = 0; nc < 16; nc++) {
            float2 bA0 = nA0, bA1 = nA1, bB0 = nB0, bB1 = nB1;
            if (nc < 15) {
                const int col = (nc + 1) * 8 + colbase;
                nA0 = *(const float2*)&bpA[col];
                nA1 = *(const float2*)&bpA[8 * 128 + col];
                nB0 = *(const float2*)&bpB[col];
                nB1 = *(const float2*)&bpB[8 * 128 + col];
            }
            uint32_t b[8];
            ldmatrix_x4(b[0], b[1], b[2], b[3], v_ld + nc * (8 * ROWB));
            ldmatrix_x4(b[4], b[5], b[6], b[7], v_ld + nc * (8 * ROWB) + 64);
            float c0[4] = {0.f, 0.f, 0.f, 0.f};
            float c1[4] = {0.f, 0.f, 0.f, 0.f};
#pragma unroll
            for (int ks = 0; ks < 4; ks++) {
                mma_f16(c0, fa0[ks * 4 + 0], fa0[ks * 4 + 1], fa0[ks * 4 + 2],
                        fa0[ks * 4 + 3], b[ks * 2], b[ks * 2 + 1]);
                mma_f16(c1, fa1[ks * 4 + 0], fa1[ks * 4 + 1], fa1[ks * 4 + 2],
                        fa1[ks * 4 + 3], b[ks * 2], b[ks * 2 + 1]);
            }
            {
                float s0 = c0[0] + bA0.x, s1 = c0[1] + bA0.y;
                float s2 = c0[2] + bA1.x, s3 = c0[3] + bA1.y;
                psA0 += s0 + s1; psA1 += s2 + s3;
                pmA0 = fmaxf(pmA0, fmaxf(s0, s1));
                pmA1 = fmaxf(pmA1, fmaxf(s2, s3));
            }
            {
                float s0 = c1[0] + bB0.x, s1 = c1[1] + bB0.y;
                float s2 = c1[2] + bB1.x, s3 = c1[3] + bB1.y;
                psB0 += s0 + s1; psB1 += s2 + s3;
                pmB0 = fmaxf(pmB0, fmaxf(s0, s1));
                pmB1 = fmaxf(pmB1, fmaxf(s2, s3));
            }
        }
        // quad reduce (cols spread over 4 tig lanes)
#pragma unroll
        for (int off = 1; off <= 2; off <<= 1) {
            psA0 += __shfl_xor_sync(0xffffffffu, psA0, off);
            psA1 += __shfl_xor_sync(0xffffffffu, psA1, off);
            psB0 += __shfl_xor_sync(0xffffffffu, psB0, off);
            psB1 += __shfl_xor_sync(0xffffffffu, psB1, off);
            pmA0 = fmaxf(pmA0, __shfl_xor_sync(0xffffffffu, pmA0, off));
            pmA1 = fmaxf(pmA1, __shfl_xor_sync(0xffffffffu, pmA1, off));
            pmB0 = fmaxf(pmB0, __shfl_xor_sync(0xffffffffu, pmB0, off));
            pmB1 = fmaxf(pmB1, __shfl_xor_sync(0xffffffffu, pmB1, off));
        }
        if (tig == 0) {
            fused[aA * 128 + browA]     = psA0 * (1.0f / 128.0f) + pmA0;
            fused[aA * 128 + browA + 8] = psA1 * (1.0f / 128.0f) + pmA1;
            fused[aB * 128 + browA]     = psB0 * (1.0f / 128.0f) + pmB0;
            fused[aB * 128 + browA + 8] = psB1 * (1.0f / 128.0f) + pmB1;
        }
    }
    __syncthreads();

    // Softmax over b for each of the 64 rows (one warp per row, round-robin)
    for (int a = wid; a < 64; a += 16) {
        float4 fv = *(float4*)&fused[a * 128 + lane * 4];
        float m = fmaxf(fmaxf(fv.x, fv.y), fmaxf(fv.z, fv.w));
#pragma unroll
        for (int off = 16; off >= 1; off >>= 1)
            m = fmaxf(m, __shfl_xor_sync(0xffffffffu, m, off));
        float e0 = __expf(fv.x - m), e1 = __expf(fv.y - m);
        float e2 = __expf(fv.z - m), e3 = __expf(fv.w - m);
        float s = (e0 + e1) + (e2 + e3);
#pragma unroll
        for (int off = 16; off >= 1; off >>= 1)
            s += __shfl_xor_sync(0xffffffffu, s, off);
        float inv = 1.0f / s;
        *(float4*)&fused[a * 128 + lane * 4] =
            make_float4(e0 * inv, e1 * inv, e2 * inv, e3 * inv);
    }
    __syncthreads();

    // attn[a, :] = sum_b w[a,b] q[b,:]; thread: a=tid/8 (64 rows), 8 cols
    {
        int a = tid >> 3;
        int dg = (tid & 7) * 8;
        float o[8];
#pragma unroll
        for (int j = 0; j < 8; j++) o[j] = 0.f;
        const float* wrow = fused + a * 128;
#pragma unroll 4
        for (int b = 0; b < 128; b++) {
            float wb = wrow[b];
            const float* qr = qs + b * 64 + dg;
            float4 q0 = *(const float4*)&qr[0];
            float4 q1 = *(const float4*)&qr[4];
            o[0] += wb * q0.x; o[1] += wb * q0.y;
            o[2] += wb * q0.z; o[3] += wb * q0.w;
            o[4] += wb * q1.x; o[5] += wb * q1.y;
            o[6] += wb * q1.z; o[7] += wb * q1.w;
        }
        int t = a0 + a;
        float* dst = g_attn2 + ((size_t)t * 8 + batch) * 512 + head * 64 + dg;
        *(float4*)&dst[0] = make_float4(o[0], o[1], o[2], o[3]);
        *(float4*)&dst[4] = make_float4(o[4], o[5], o[6], o[7]);
    }
}

// ---------------------------------------------------------------------------
extern "C" void kernel_launch(void* const* d_in, const int* in_sizes, int n_in,
                              void* d_out, int out_size)
{
    const float* query = (const float*)d_in[0];
    const float* key   = (const float*)d_in[1];
    const float* value = (const float*)d_in[2];
    const float* cbias = (const float*)d_in[3];
    const float* ipw   = (const float*)d_in[4];
    const float* ipb   = (const float*)d_in[5];
    const float* outw  = (const float*)d_in[6];
    const float* outb  = (const float*)d_in[7];
    float* out = (float*)d_out;

    cudaFuncSetAttribute(gemm_proj_kernel,
                         cudaFuncAttributeMaxDynamicSharedMemorySize, PJ_TOTAL);
    // in-projection on tensor cores (3-term fp16 split, fp32-accurate)
    gemm_proj_kernel<<<dim3(24, 16), 256, PJ_TOTAL>>>(query, key, value, ipw,
                                                      ipb, nullptr, 0);

    cudaFuncSetAttribute(tri_main_v8,
                         cudaFuncAttributeMaxDynamicSharedMemorySize, SM_TOTAL);
    tri_main_v8<<<dim3(8, 2, 8), 512, SM_TOTAL>>>(cbias);

    // out-projection (X = g_attn2 selected inside kernel via mode=1)
    gemm_proj_kernel<<<dim3(8, 16), 256, PJ_TOTAL>>>(nullptr, nullptr,
                                                     nullptr, outw, outb,
                                                     out, 1);
}